// round 13
// baseline (speedup 1.0000x reference)
#include <cuda_runtime.h>
#include <cuda_bf16.h>
#include <cstdint>

// ============================================================================
// C = tril(tril(A) @ tril(B)), N=4096, fp32.
// R10 re-bench (prior round: broker infra failure, kernel never ran):
// 2 CTAs/SM (launch_bounds(256,2), regs<=128), k32 chunks, 3-stage
// cp.async pipeline (3x32KB smem), 128x128 tile, 8 warps of 64x32,
// [Ah|Al] interleaved 128B rows (SW128), 3-term bf16 split, fused prologue.
// ============================================================================

#define NN 4096
#define NT 32
#define N_LOWER 528
#define STAGE32 32768          // A tile 16KB ([Ah32|Al32] rows) + B tile 16KB
#define OFF_B 16384
#define NSTAGE 3
#define SMEM_DYN (NSTAGE*STAGE32 + 1024)

__device__ __nv_bfloat16 g_Ah[(size_t)NN*NN];
__device__ __nv_bfloat16 g_Al[(size_t)NN*NN];
__device__ __nv_bfloat16 g_Bh[(size_t)NN*NN];
__device__ __nv_bfloat16 g_Bl[(size_t)NN*NN];

__device__ __forceinline__ uint32_t smem_u32(const void* p) {
    return (uint32_t)__cvta_generic_to_shared(p);
}
#define CP_ASYNC16(dst, src) \
    asm volatile("cp.async.cg.shared.global [%0], [%1], 16;" :: "r"(dst), "l"(src) : "memory")
#define CP_COMMIT() asm volatile("cp.async.commit_group;" ::: "memory")
#define CP_WAIT0()  asm volatile("cp.async.wait_group 0;" ::: "memory")
#define CP_WAIT1()  asm volatile("cp.async.wait_group 1;" ::: "memory")
#define CP_WAIT2()  asm volatile("cp.async.wait_group 2;" ::: "memory")

__device__ __forceinline__ void ldmx4(uint32_t* r, uint32_t addr) {
    asm volatile("ldmatrix.sync.aligned.m8n8.x4.shared.b16 {%0,%1,%2,%3}, [%4];"
        : "=r"(r[0]), "=r"(r[1]), "=r"(r[2]), "=r"(r[3]) : "r"(addr));
}
__device__ __forceinline__ void mma16816(float* d, const uint32_t* a, uint32_t b0, uint32_t b1) {
    asm volatile("mma.sync.aligned.m16n8k16.row.col.f32.bf16.bf16.f32 "
        "{%0,%1,%2,%3}, {%4,%5,%6,%7}, {%8,%9}, {%0,%1,%2,%3};"
        : "+f"(d[0]), "+f"(d[1]), "+f"(d[2]), "+f"(d[3])
        : "r"(a[0]), "r"(a[1]), "r"(a[2]), "r"(a[3]), "r"(b0), "r"(b1));
}
__device__ __forceinline__ uint32_t sw128(uint32_t off) {
    return off ^ ((off >> 3) & 0x70);
}

// ---------------------------- fused split prologue ---------------------------
__global__ void __launch_bounds__(256) split_fused_kernel(const float* __restrict__ A,
                                                          const float* __restrict__ B) {
    const int tid = threadIdx.x;
    if (blockIdx.x < 16384) {
        size_t idx = ((size_t)blockIdx.x * 256 + tid) * 4;
        int i = (int)(idx >> 12);
        int k = (int)(idx & 4095);
        float4 a = *(const float4*)(A + idx);
        float v[4] = {a.x, a.y, a.z, a.w};
        struct alignas(8) BF4 { __nv_bfloat16 v[4]; };
        BF4 H, L;
#pragma unroll
        for (int t = 0; t < 4; ++t) {
            float x = (k + t <= i) ? v[t] : 0.f;
            __nv_bfloat16 xh = __float2bfloat16(x);
            H.v[t] = xh;
            L.v[t] = __float2bfloat16(x - __bfloat162float(xh));
        }
        *(BF4*)(g_Ah + idx) = H;
        *(BF4*)(g_Al + idx) = L;
    } else {
        __shared__ float tile[32][33];
        int bid = blockIdx.x - 16384;
        int bx = bid & 127, by = bid >> 7;
        int tx = tid & 31, ty = tid >> 5;     // (32, 8)
        int j = bx * 32 + tx;
#pragma unroll
        for (int s = 0; s < 4; ++s) {
            int k = by * 32 + ty + s * 8;
            tile[ty + s * 8][tx] = (k >= j) ? B[(size_t)k * NN + j] : 0.f;
        }
        __syncthreads();
        int k2 = by * 32 + tx;
#pragma unroll
        for (int s = 0; s < 4; ++s) {
            int j2 = bx * 32 + ty + s * 8;
            float x = tile[tx][ty + s * 8];
            __nv_bfloat16 xh = __float2bfloat16(x);
            __nv_bfloat16 xl = __float2bfloat16(x - __bfloat162float(xh));
            g_Bh[(size_t)j2 * NN + k2] = xh;
            g_Bl[(size_t)j2 * NN + k2] = xl;
        }
    }
}

// ---------------------------- main GEMM kernel ------------------------------
// One k32 chunk = 32KB: A rows [Ah(64B)|Al(64B)], B rows likewise.
// 256 threads x 8 cp.async.
__device__ __forceinline__ void load_chunk32(uint32_t base, int bi, int bj, int c, int tid) {
    const int k0 = c * 32;
    const int u = tid & 7;           // 16B unit within 128B row
    const int uu = u & 3;
    const int r0 = tid >> 3;         // 0..31
    const __nv_bfloat16* gA = (u < 4) ? g_Ah : g_Al;
    const __nv_bfloat16* gB = (u < 4) ? g_Bh : g_Bl;
    const size_t col = (size_t)(k0 + uu * 8);
#pragma unroll
    for (int p = 0; p < 4; ++p) {
        int row = p * 32 + r0;
        uint32_t sw = sw128(row * 128 + u * 16);
        CP_ASYNC16(base + sw, gA + (size_t)(bi * 128 + row) * NN + col);
    }
#pragma unroll
    for (int p = 0; p < 4; ++p) {
        int row = p * 32 + r0;
        uint32_t sw = sw128(row * 128 + u * 16);
        CP_ASYNC16(base + OFF_B + sw, gB + (size_t)(bj * 128 + row) * NN + col);
    }
    CP_COMMIT();
}

// 64x32 warp tile, one k32 chunk (2 k16 steps), 3-term split.
__device__ __forceinline__ void compute_chunk32(uint32_t base, uint32_t a_row, uint32_t b_row,
                                                uint32_t hi16, float acc[4][4][4]) {
#pragma unroll
    for (int ks = 0; ks < 2; ++ks) {
        const uint32_t kb = ks * 32 + hi16;
        uint32_t ah[4][4], al[4][4], bh[2][4], bl[2][4];
#pragma unroll
        for (int mt = 0; mt < 4; ++mt) {
            uint32_t roff = (a_row + mt * 16) * 128;
            ldmx4(ah[mt], base + sw128(roff + kb));
            ldmx4(al[mt], base + sw128(roff + 64 + kb));
        }
#pragma unroll
        for (int nt2 = 0; nt2 < 2; ++nt2) {
            uint32_t roff = (b_row + nt2 * 16) * 128;
            ldmx4(bh[nt2], base + OFF_B + sw128(roff + kb));
            ldmx4(bl[nt2], base + OFF_B + sw128(roff + 64 + kb));
        }
#pragma unroll
        for (int mt = 0; mt < 4; ++mt)
#pragma unroll
            for (int nt = 0; nt < 4; ++nt) {
                const int g2 = nt >> 1, o = nt & 1;
                mma16816(acc[mt][nt], ah[mt], bh[g2][o], bh[g2][o + 2]);
            }
#pragma unroll
        for (int mt = 0; mt < 4; ++mt)
#pragma unroll
            for (int nt = 0; nt < 4; ++nt) {
                const int g2 = nt >> 1, o = nt & 1;
                mma16816(acc[mt][nt], al[mt], bh[g2][o], bh[g2][o + 2]);
            }
#pragma unroll
        for (int mt = 0; mt < 4; ++mt)
#pragma unroll
            for (int nt = 0; nt < 4; ++nt) {
                const int g2 = nt >> 1, o = nt & 1;
                mma16816(acc[mt][nt], ah[mt], bl[g2][o], bl[g2][o + 2]);
            }
    }
}

__global__ void __launch_bounds__(256, 2) trimm_kernel(float* __restrict__ C) {
    const int id = blockIdx.x;
    const int tid = threadIdx.x;
    int bi, bj;

    if (id >= N_LOWER) {
        int r = id - N_LOWER;
        bi = 0; bj = 1;
        for (int ii = 0; ii < 31; ++ii) {
            int sz = 31 - ii;
            if (r < sz) { bi = ii; bj = ii + 1 + r; break; }
            r -= sz;
        }
        size_t row0 = (size_t)bi * 128, col0 = (size_t)bj * 128;
        float4 z = make_float4(0.f, 0.f, 0.f, 0.f);
        for (int e = tid; e < 128 * 32; e += 256) {
            int rr = e >> 5, c4 = e & 31;
            *(float4*)(C + (row0 + rr) * NN + col0 + c4 * 4) = z;
        }
        return;
    }

    {   // lower tiles, longest k-range first (LPT for 2-CTA/SM packing)
        int rem = id, d = 0;
        for (int dd = 31; dd >= 0; --dd) {
            int sz = 32 - dd;
            if (rem < sz) { d = dd; break; }
            rem -= sz;
        }
        bj = rem; bi = rem + d;
    }

    extern __shared__ char smem_raw[];
    uint32_t smem_u = smem_u32(smem_raw);
    uint32_t tb = (smem_u + 1023) & ~1023u;

    const int wid = tid >> 5, lane = tid & 31;
    const int wm = wid >> 2, wn = wid & 3;
    const uint32_t a_row = wm * 64 + (lane & 15);
    const uint32_t b_row = wn * 32 + (lane & 15);
    const uint32_t hi16 = (lane >> 4) * 16;

    float acc[4][4][4];
#pragma unroll
    for (int a = 0; a < 4; ++a)
#pragma unroll
        for (int b = 0; b < 4; ++b)
#pragma unroll
            for (int c = 0; c < 4; ++c) acc[a][b][c] = 0.f;

    const int c0 = bj * 4;
    const int nc = (bi - bj + 1) * 4;     // k32 chunks, >= 4

    load_chunk32(tb,               bi, bj, c0,     tid);
    load_chunk32(tb + STAGE32,     bi, bj, c0 + 1, tid);
    load_chunk32(tb + 2 * STAGE32, bi, bj, c0 + 2, tid);

    uint32_t st = tb;
    for (int i = 0; i < nc; ++i) {
        const int rem = nc - i;
        if (rem >= 3) CP_WAIT2();
        else if (rem == 2) CP_WAIT1();
        else CP_WAIT0();
        __syncthreads();
        compute_chunk32(st, a_row, b_row, hi16, acc);
        __syncthreads();
        if (i + 3 < nc) load_chunk32(st, bi, bj, c0 + i + 3, tid);
        st += STAGE32;
        if (st == tb + NSTAGE * STAGE32) st = tb;
    }

    // Epilogue: upper triangle exactly zero by construction; direct stores.
    const int row_base = bi * 128 + wm * 64 + (lane >> 2);
    const int col_base = bj * 128 + wn * 32 + (lane & 3) * 2;
#pragma unroll
    for (int mt = 0; mt < 4; ++mt)
#pragma unroll
        for (int nt = 0; nt < 4; ++nt) {
            int rg = row_base + mt * 16;
            int cg = col_base + nt * 8;
            *(float2*)(C + (size_t)rg * NN + cg)       = make_float2(acc[mt][nt][0], acc[mt][nt][1]);
            *(float2*)(C + (size_t)(rg + 8) * NN + cg) = make_float2(acc[mt][nt][2], acc[mt][nt][3]);
        }
}

// ---------------------------- launch ----------------------------------------
extern "C" void kernel_launch(void* const* d_in, const int* in_sizes, int n_in,
                              void* d_out, int out_size) {
    (void)in_sizes; (void)n_in; (void)out_size;
    const float* A = (const float*)d_in[0];
    const float* B = (const float*)d_in[1];
    float* C = (float*)d_out;

    split_fused_kernel<<<32768, 256>>>(A, B);

    cudaFuncSetAttribute(trimm_kernel, cudaFuncAttributeMaxDynamicSharedMemorySize, SMEM_DYN);
    trimm_kernel<<<NT * NT, 256, SMEM_DYN>>>(C);
}

// round 16
// speedup vs baseline: 1.2475x; 1.2475x over previous
#include <cuda_runtime.h>
#include <cuda_bf16.h>
#include <cstdint>

// ============================================================================
// C = tril(tril(A) @ tril(B)), N=4096, fp32.
// R14 re-bench (prior round: broker infra failure, kernel never ran):
//  - 1 CTA/SM + k64 chunks (best measured structure)
//  - 3-stage cp.async pipeline (3x64KB), ONE __syncthreads per chunk
//  - triangle-only split prologue (skip never-read tiles, ~48% less traffic)
// 128x128 tile, 8 warps of 64x32, SW128, 3-term bf16 hi/lo split.
// ============================================================================

#define NN 4096
#define NT 32
#define N_LOWER 528
#define STAGE 65536           // Ah,Al,Bh,Bl tiles (16KB each)
#define OFF_AH 0
#define OFF_AL 16384
#define OFF_BH 32768
#define OFF_BL 49152
#define NSTAGE 3
#define SMEM_DYN (NSTAGE*STAGE + 1024)
#define L32 8256              // 128*129/2 lower 32x32 tiles

__device__ __nv_bfloat16 g_Ah[(size_t)NN*NN];
__device__ __nv_bfloat16 g_Al[(size_t)NN*NN];
__device__ __nv_bfloat16 g_Bh[(size_t)NN*NN];
__device__ __nv_bfloat16 g_Bl[(size_t)NN*NN];

__device__ __forceinline__ uint32_t smem_u32(const void* p) {
    return (uint32_t)__cvta_generic_to_shared(p);
}
#define CP_ASYNC16(dst, src) \
    asm volatile("cp.async.cg.shared.global [%0], [%1], 16;" :: "r"(dst), "l"(src) : "memory")
#define CP_COMMIT() asm volatile("cp.async.commit_group;" ::: "memory")
#define CP_WAIT0()  asm volatile("cp.async.wait_group 0;" ::: "memory")
#define CP_WAIT1()  asm volatile("cp.async.wait_group 1;" ::: "memory")

__device__ __forceinline__ void ldmx4(uint32_t* r, uint32_t addr) {
    asm volatile("ldmatrix.sync.aligned.m8n8.x4.shared.b16 {%0,%1,%2,%3}, [%4];"
        : "=r"(r[0]), "=r"(r[1]), "=r"(r[2]), "=r"(r[3]) : "r"(addr));
}
__device__ __forceinline__ void mma16816(float* d, const uint32_t* a, uint32_t b0, uint32_t b1) {
    asm volatile("mma.sync.aligned.m16n8k16.row.col.f32.bf16.bf16.f32 "
        "{%0,%1,%2,%3}, {%4,%5,%6,%7}, {%8,%9}, {%0,%1,%2,%3};"
        : "+f"(d[0]), "+f"(d[1]), "+f"(d[2]), "+f"(d[3])
        : "r"(a[0]), "r"(a[1]), "r"(a[2]), "r"(a[3]), "r"(b0), "r"(b1));
}
__device__ __forceinline__ uint32_t sw128(uint32_t off) {
    return off ^ ((off >> 3) & 0x70);
}

// ---------------------------- triangle-only prologue -------------------------
// Decode linear lower-triangle index r -> (hi, lo) with lo <= hi.
__device__ __forceinline__ void tri_decode(int r, int& hi, int& lo) {
    int t = (int)((sqrtf(8.f * (float)r + 1.f) - 1.f) * 0.5f);
    while ((t + 1) * (t + 2) / 2 <= r) ++t;
    while (t * (t + 1) / 2 > r) --t;
    hi = t; lo = r - t * (t + 1) / 2;
}

// Blocks [0, L32): A tiles (i_blk, k_blk), k_blk <= i_blk. Mask on diag.
// Blocks [L32, 2*L32): B tiles (j_blk, k_blk), k_blk >= j_blk, transposed.
__global__ void __launch_bounds__(256) split_tri_kernel(const float* __restrict__ A,
                                                        const float* __restrict__ B) {
    const int tid = threadIdx.x;
    if (blockIdx.x < L32) {
        int ti, tk; tri_decode(blockIdx.x, ti, tk);
        const int i0 = ti * 32, k0 = tk * 32;
        const int row = i0 + (tid >> 3);
        const int col = k0 + (tid & 7) * 4;
        const bool diag = (ti == tk);
        float4 a = *(const float4*)(A + (size_t)row * NN + col);
        float v[4] = {a.x, a.y, a.z, a.w};
        struct alignas(8) BF4 { __nv_bfloat16 v[4]; };
        BF4 H, L;
#pragma unroll
        for (int t = 0; t < 4; ++t) {
            float x = (!diag || (col + t <= row)) ? v[t] : 0.f;
            __nv_bfloat16 xh = __float2bfloat16(x);
            H.v[t] = xh;
            L.v[t] = __float2bfloat16(x - __bfloat162float(xh));
        }
        *(BF4*)(g_Ah + (size_t)row * NN + col) = H;
        *(BF4*)(g_Al + (size_t)row * NN + col) = L;
    } else {
        int hi, lo; tri_decode(blockIdx.x - L32, hi, lo);
        const int tk = hi, tj = lo;              // k_blk >= j_blk
        const int k0 = tk * 32, j0 = tj * 32;
        const bool diag = (tk == tj);
        __shared__ float tile[32][33];
        const int tx = tid & 31, ty = tid >> 5;  // (32, 8)
        const int j = j0 + tx;
#pragma unroll
        for (int s = 0; s < 4; ++s) {
            int k = k0 + ty + s * 8;
            tile[ty + s * 8][tx] = (!diag || (k >= j)) ? B[(size_t)k * NN + j] : 0.f;
        }
        __syncthreads();
        const int k2 = k0 + tx;
#pragma unroll
        for (int s = 0; s < 4; ++s) {
            int j2 = j0 + ty + s * 8;
            float x = tile[tx][ty + s * 8];
            __nv_bfloat16 xh = __float2bfloat16(x);
            __nv_bfloat16 xl = __float2bfloat16(x - __bfloat162float(xh));
            g_Bh[(size_t)j2 * NN + k2] = xh;
            g_Bl[(size_t)j2 * NN + k2] = xl;
        }
    }
}

// ---------------------------- main GEMM kernel ------------------------------
__device__ __forceinline__ void load_tile_async(uint32_t sdst, const __nv_bfloat16* __restrict__ g,
                                                int row0, int k0, int tid) {
    const int u = tid & 7;
    const int r0 = tid >> 3;
#pragma unroll
    for (int p = 0; p < 4; ++p) {
        int row = p * 32 + r0;
        uint32_t off = row * 128 + u * 16;
        CP_ASYNC16(sdst + sw128(off), g + (size_t)(row0 + row) * NN + k0 + u * 8);
    }
}
__device__ __forceinline__ void load_chunk(uint32_t base, int bi, int bj, int chunk, int tid) {
    int k0 = chunk * 64;
    load_tile_async(base + OFF_AH, g_Ah, bi * 128, k0, tid);
    load_tile_async(base + OFF_AL, g_Al, bi * 128, k0, tid);
    load_tile_async(base + OFF_BH, g_Bh, bj * 128, k0, tid);
    load_tile_async(base + OFF_BL, g_Bl, bj * 128, k0, tid);
    CP_COMMIT();
}

// 64x32 warp tile, one k64 chunk (4 k16 steps), 3-term split, term-major.
__device__ __forceinline__ void compute_chunk(uint32_t base, uint32_t a_row, uint32_t b_row,
                                              uint32_t hi16, float acc[4][4][4]) {
#pragma unroll
    for (int ks = 0; ks < 4; ++ks) {
        const uint32_t kb = ks * 32 + hi16;
        uint32_t ah[4][4], al[4][4], bh[2][4], bl[2][4];
#pragma unroll
        for (int mt = 0; mt < 4; ++mt) {
            uint32_t sw = sw128((a_row + mt * 16) * 128 + kb);
            ldmx4(ah[mt], base + OFF_AH + sw);
            ldmx4(al[mt], base + OFF_AL + sw);
        }
#pragma unroll
        for (int nt2 = 0; nt2 < 2; ++nt2) {
            uint32_t sw = sw128((b_row + nt2 * 16) * 128 + kb);
            ldmx4(bh[nt2], base + OFF_BH + sw);
            ldmx4(bl[nt2], base + OFF_BL + sw);
        }
#pragma unroll
        for (int mt = 0; mt < 4; ++mt)
#pragma unroll
            for (int nt = 0; nt < 4; ++nt) {
                const int g2 = nt >> 1, o = nt & 1;
                mma16816(acc[mt][nt], ah[mt], bh[g2][o], bh[g2][o + 2]);
            }
#pragma unroll
        for (int mt = 0; mt < 4; ++mt)
#pragma unroll
            for (int nt = 0; nt < 4; ++nt) {
                const int g2 = nt >> 1, o = nt & 1;
                mma16816(acc[mt][nt], al[mt], bh[g2][o], bh[g2][o + 2]);
            }
#pragma unroll
        for (int mt = 0; mt < 4; ++mt)
#pragma unroll
            for (int nt = 0; nt < 4; ++nt) {
                const int g2 = nt >> 1, o = nt & 1;
                mma16816(acc[mt][nt], ah[mt], bl[g2][o], bl[g2][o + 2]);
            }
    }
}

__global__ void __launch_bounds__(256, 1) trimm_kernel(float* __restrict__ C) {
    const int id = blockIdx.x;
    const int tid = threadIdx.x;
    int bi, bj;

    if (id >= N_LOWER) {
        int r = id - N_LOWER;
        bi = 0; bj = 1;
        for (int ii = 0; ii < 31; ++ii) {
            int sz = 31 - ii;
            if (r < sz) { bi = ii; bj = ii + 1 + r; break; }
            r -= sz;
        }
        size_t row0 = (size_t)bi * 128, col0 = (size_t)bj * 128;
        float4 z = make_float4(0.f, 0.f, 0.f, 0.f);
        for (int e = tid; e < 128 * 32; e += 256) {
            int rr = e >> 5, c4 = e & 31;
            *(float4*)(C + (row0 + rr) * NN + col0 + c4 * 4) = z;
        }
        return;
    }

    {   // lower tiles, longest k-range first
        int rem = id, d = 0;
        for (int dd = 31; dd >= 0; --dd) {
            int sz = 32 - dd;
            if (rem < sz) { d = dd; break; }
            rem -= sz;
        }
        bj = rem; bi = rem + d;
    }

    extern __shared__ char smem_raw[];
    uint32_t smem_u = smem_u32(smem_raw);
    uint32_t tb = (smem_u + 1023) & ~1023u;

    const int wid = tid >> 5, lane = tid & 31;
    const int wm = wid >> 2, wn = wid & 3;
    const uint32_t a_row = wm * 64 + (lane & 15);
    const uint32_t b_row = wn * 32 + (lane & 15);
    const uint32_t hi16 = (lane >> 4) * 16;

    float acc[4][4][4];
#pragma unroll
    for (int a = 0; a < 4; ++a)
#pragma unroll
        for (int b = 0; b < 4; ++b)
#pragma unroll
            for (int c = 0; c < 4; ++c) acc[a][b][c] = 0.f;

    const int c0 = bj * 2;
    const int nc = (bi - bj + 1) * 2;   // k64 chunks, >= 2

    // 3-stage pipeline, chunk c -> stage c%3, ONE barrier per chunk.
    load_chunk(tb,          bi, bj, c0,     tid);
    load_chunk(tb + STAGE,  bi, bj, c0 + 1, tid);

    for (int i = 0; i < nc; ++i) {
        if (i + 1 < nc) CP_WAIT1(); else CP_WAIT0();
        __syncthreads();   // all warps finished chunk i-1 -> stage (i-1)%3 reusable
        if (i + 2 < nc) {
            int s = (i + 2) % 3;
            load_chunk(tb + s * STAGE, bi, bj, c0 + i + 2, tid);
        }
        compute_chunk(tb + (i % 3) * STAGE, a_row, b_row, hi16, acc);
    }

    // Epilogue: upper triangle exactly zero by construction; direct stores.
    const int row_base = bi * 128 + wm * 64 + (lane >> 2);
    const int col_base = bj * 128 + wn * 32 + (lane & 3) * 2;
#pragma unroll
    for (int mt = 0; mt < 4; ++mt)
#pragma unroll
        for (int nt = 0; nt < 4; ++nt) {
            int rg = row_base + mt * 16;
            int cg = col_base + nt * 8;
            *(float2*)(C + (size_t)rg * NN + cg)       = make_float2(acc[mt][nt][0], acc[mt][nt][1]);
            *(float2*)(C + (size_t)(rg + 8) * NN + cg) = make_float2(acc[mt][nt][2], acc[mt][nt][3]);
        }
}

// ---------------------------- launch ----------------------------------------
extern "C" void kernel_launch(void* const* d_in, const int* in_sizes, int n_in,
                              void* d_out, int out_size) {
    (void)in_sizes; (void)n_in; (void)out_size;
    const float* A = (const float*)d_in[0];
    const float* B = (const float*)d_in[1];
    float* C = (float*)d_out;

    split_tri_kernel<<<2 * L32, 256>>>(A, B);

    cudaFuncSetAttribute(trimm_kernel, cudaFuncAttributeMaxDynamicSharedMemorySize, SMEM_DYN);
    trimm_kernel<<<NT * NT, 256, SMEM_DYN>>>(C);
}